// round 7
// baseline (speedup 1.0000x reference)
#include <cuda_runtime.h>
#include <mma.h>
#include <cstdint>

using namespace nvcuda;

#define T_STEPS 1024
#define B_SZ    64
#define H_SZ    1024
#define BH      (B_SZ * H_SZ)          /* 65536 */
#define TBH     (T_STEPS * BH)

// ---------------- scan config ----------------
#define RSZ   16         // batch rows per block
#define CSZ   32         // output cols per block
#define NBLK  128        // 4 row-groups x 32 col-blocks
#define KCH   64         // k columns per warp chunk
#define NWARP 16
#define SST   36         // stage row stride (floats)
#define FPAD  32         // one flag per 128B L2 line
#define NFLG  (NBLK * NWARP)

__device__ unsigned g_wflags[NFLG * FPAD];       // per-warp progress flags
__device__ __align__(16) float g_hswz[2][BH];    // fragment-major h ping-pong

// ---------------- asm helpers ----------------
__device__ __forceinline__ unsigned ldacq(const unsigned* p) {
    unsigned v;
    asm volatile("ld.acquire.gpu.global.u32 %0, [%1];" : "=r"(v) : "l"(p));
    return v;
}
__device__ __forceinline__ unsigned ldflag(const unsigned* p) {
    unsigned v;
    asm volatile("ld.global.cg.u32 %0, [%1];" : "=r"(v) : "l"(p));
    return v;
}
__device__ __forceinline__ void strel(unsigned* p, unsigned v) {
    asm volatile("st.release.gpu.global.u32 [%0], %1;" :: "l"(p), "r"(v) : "memory");
}
__device__ __forceinline__ void cp16(float* s, const float* g) {
    unsigned sa = (unsigned)__cvta_generic_to_shared(s);
    asm volatile("cp.async.cg.shared.global [%0], [%1], 16;" :: "r"(sa), "l"(g));
}
__device__ __forceinline__ void cpcommit() { asm volatile("cp.async.commit_group;"); }
template<int N> __device__ __forceinline__ void cpwait() {
    asm volatile("cp.async.wait_group %0;" :: "n"(N));
}
__device__ __forceinline__ void mma_tf32(float acc[4], const uint4& a, const unsigned b[2]) {
    asm volatile("mma.sync.aligned.m16n8k8.row.col.f32.tf32.tf32.f32 "
                 "{%0,%1,%2,%3}, {%4,%5,%6,%7}, {%8,%9}, {%0,%1,%2,%3};"
                 : "+f"(acc[0]), "+f"(acc[1]), "+f"(acc[2]), "+f"(acc[3])
                 : "r"(a.x), "r"(a.y), "r"(a.z), "r"(a.w), "r"(b[0]), "r"(b[1]));
}

// ---------------------------------------------------------------------------
// Kernel A: xproj = xs @ Wih — cp.async 2-stage pipelined, 128x128x32 tiles.
// Raw fp32 staged via cp.async; tf32 HMMA truncates operands in HW.
// ---------------------------------------------------------------------------
__global__ void __launch_bounds__(256) xproj_gemm(const float* __restrict__ xs,
                                                  const float* __restrict__ Wih,
                                                  float* __restrict__ C) {
    extern __shared__ float xsm[];
    float* As = xsm;                  // 2 stages x 128*36
    float* Bs = xsm + 2 * 128 * 36;   // 2 stages x 32*136

    const int tid = threadIdx.x;
    const int m0  = blockIdx.y * 128;
    const int n0  = blockIdx.x * 128;
    const int w   = tid >> 5;
    const int wm  = w >> 1;
    const int wn  = w & 1;

    wmma::fragment<wmma::accumulator, 16, 16, 8, float> cf[2][4];
#pragma unroll
    for (int i = 0; i < 2; i++)
#pragma unroll
        for (int j = 0; j < 4; j++) wmma::fill_fragment(cf[i][j], 0.0f);

    auto loadStage = [&](int s, int kt) {
        float* a = As + s * (128 * 36);
#pragma unroll
        for (int i = 0; i < 4; i++) {
            int idx = tid + i * 256;
            int r = idx >> 3, q = (idx & 7) * 4;
            cp16(a + r * 36 + q, xs + (size_t)(m0 + r) * H_SZ + kt + q);
        }
        float* b = Bs + s * (32 * 136);
#pragma unroll
        for (int i = 0; i < 4; i++) {
            int idx = tid + i * 256;
            int r = idx >> 5, q = (idx & 31) * 4;
            cp16(b + r * 136 + q, Wih + (size_t)(kt + r) * H_SZ + n0 + q);
        }
        cpcommit();
    };

    loadStage(0, 0);

    for (int kt32 = 0; kt32 < 32; kt32++) {
        if (kt32 + 1 < 32) {
            loadStage((kt32 + 1) & 1, (kt32 + 1) * 32);
            cpwait<1>();
        } else {
            cpwait<0>();
        }
        __syncthreads();

        const float* a = As + (kt32 & 1) * (128 * 36);
        const float* b = Bs + (kt32 & 1) * (32 * 136);
#pragma unroll
        for (int kk = 0; kk < 4; kk++) {
            wmma::fragment<wmma::matrix_a, 16, 16, 8, wmma::precision::tf32, wmma::row_major> af[2];
            wmma::fragment<wmma::matrix_b, 16, 16, 8, wmma::precision::tf32, wmma::row_major> bf[4];
            wmma::load_matrix_sync(af[0], a + (wm * 32 + 0)  * 36 + kk * 8, 36);
            wmma::load_matrix_sync(af[1], a + (wm * 32 + 16) * 36 + kk * 8, 36);
#pragma unroll
            for (int j = 0; j < 4; j++)
                wmma::load_matrix_sync(bf[j], b + (kk * 8) * 136 + wn * 64 + j * 16, 136);
#pragma unroll
            for (int i = 0; i < 2; i++)
#pragma unroll
                for (int j = 0; j < 4; j++)
                    wmma::mma_sync(cf[i][j], af[i], bf[j], cf[i][j]);
        }
        __syncthreads();
    }

#pragma unroll
    for (int i = 0; i < 2; i++)
#pragma unroll
        for (int j = 0; j < 4; j++)
            wmma::store_matrix_sync(
                C + (size_t)(m0 + wm * 32 + i * 16) * H_SZ + n0 + wn * 64 + j * 16,
                cf[i][j], H_SZ, wmma::mem_row_major);
}

// ---------------------------------------------------------------------------
// Swizzle init -> g_hswz[1]  (slot (t+1)&1 is read at step t)
// ---------------------------------------------------------------------------
__global__ void swizzle_init(const float* __restrict__ init) {
    int idx = blockIdx.x * 256 + threadIdx.x;        // 0..65535
    int r = idx >> 10, gcol = idx & 1023;
    int rb = r >> 4, r16 = r & 15;
    int c = gcol >> 6, kk = (gcol >> 3) & 7, tcol = gcol & 7;
    int reg  = ((r16 >= 8) ? 1 : 0) | ((tcol >= 4) ? 2 : 0);
    int lane = 4 * (r16 & 7) + (tcol & 3);
    g_hswz[1][rb * 16384 + ((c * 8 + kk) * 32 + lane) * 4 + reg] =
        wmma::__float_to_tf32(init[idx]);
}

// ---------------------------------------------------------------------------
// Kernel B: persistent scan, warp-granular flags.
// Warp w of block (rb,jb): row er=w, chunk c=(w+jb)&15, Whh fragments in
// registers. Per step: poll 32 producer-warp flags (1/lane), LDG.128 A
// fragments from swizzled ping-pong, 32 MMAs, STS partials (parity buffer),
// ONE block barrier, reduce+tanh, dual store, own-warp release.
// ---------------------------------------------------------------------------
__global__ void __launch_bounds__(512) rnn_scan(const float* __restrict__ Whh,
                                                const float* __restrict__ bih,
                                                const float* __restrict__ bhh,
                                                float* __restrict__ outs,
                                                float* __restrict__ carry) {
    extern __shared__ float stage[];                 // [2][NWARP*RSZ*SST]

    const int tid = threadIdx.x, bid = blockIdx.x;
    const int rb = bid & 3, jb = bid >> 2;
    const int r0 = rb * RSZ, j0 = jb * CSZ;
    const int w = tid >> 5, lane = tid & 31;
    const int g = lane >> 2, tg = lane & 3;
    const int c = (w + jb) & 15;                     // staggered chunk
    const int er = w, ec = lane;                     // this thread's h element

    unsigned* myflag = &g_wflags[(bid * NWARP + w) * FPAD];
    const unsigned base = ldflag(myflag);
    const float bsum = bih[j0 + ec] + bhh[j0 + ec];

    // swizzle slot for produced h element (er, j0+ec)
    const int pgc = j0 + ec;
    const int preg  = ((er >= 8) ? 1 : 0) | (((pgc & 7) >= 4) ? 2 : 0);
    const int plane = 4 * (er & 7) + (pgc & 3);
    const int swz_off = rb * 16384 +
        (((pgc >> 6) * 8 + ((pgc >> 3) & 7)) * 32 + plane) * 4 + preg;

    // producer-warp flag for this lane: block (rb, 2c+(lane>>4)), warp lane&15
    const unsigned* pflag =
        &g_wflags[((((unsigned)(2 * c + (lane >> 4)) << 2) | (unsigned)rb) * NWARP
                   + (lane & 15)) * FPAD];

    // Whh fragments: 8 ksteps x 4 ntiles x 2 regs = 64 registers, persistent
    unsigned Bf[8][4][2];
#pragma unroll
    for (int kk = 0; kk < 8; kk++)
#pragma unroll
        for (int nt = 0; nt < 4; nt++) {
            int krow = c * KCH + kk * 8 + tg;
            int ncol = j0 + nt * 8 + g;
            Bf[kk][nt][0] = __float_as_uint(
                wmma::__float_to_tf32(Whh[(size_t)krow * H_SZ + ncol]));
            Bf[kk][nt][1] = __float_as_uint(
                wmma::__float_to_tf32(Whh[(size_t)(krow + 4) * H_SZ + ncol]));
        }

#pragma unroll 1
    for (int t = 0; t < T_STEPS; t++) {
        const size_t ooff = (size_t)t * BH + (size_t)(r0 + er) * H_SZ + j0 + ec;
        const float xp = __ldcg(outs + ooff);

        if (t > 0) {
            for (;;) {
                int ok = (int)(ldflag(pflag) - base) >= t;
                if (__all_sync(0xffffffffu, ok)) break;
                __nanosleep(16);
            }
            (void)ldacq(pflag);                      // acquire once per step
        }

        // A fragments: 8 coalesced LDG.128 from swizzled h_{t-1}
        const uint4* ap = reinterpret_cast<const uint4*>(
            g_hswz[(t + 1) & 1] + rb * 16384 + (c * 8) * 128) + lane;

        float acc[4][4] = {{0,0,0,0},{0,0,0,0},{0,0,0,0},{0,0,0,0}};
        uint4 av = __ldcg(ap);
#pragma unroll
        for (int kk = 0; kk < 8; kk++) {
            uint4 nx;
            if (kk < 7) nx = __ldcg(ap + (kk + 1) * 32);
#pragma unroll
            for (int nt = 0; nt < 4; nt++)
                mma_tf32(acc[nt], av, Bf[kk][nt]);
            av = nx;
        }

        // stage partials into parity buffer
        float* sb = stage + (t & 1) * (NWARP * RSZ * SST);
        float* stg = sb + w * (RSZ * SST);
#pragma unroll
        for (int nt = 0; nt < 4; nt++) {
            *reinterpret_cast<float2*>(stg + g * SST + nt * 8 + 2 * tg) =
                make_float2(acc[nt][0], acc[nt][1]);
            *reinterpret_cast<float2*>(stg + (g + 8) * SST + nt * 8 + 2 * tg) =
                make_float2(acc[nt][2], acc[nt][3]);
        }
        __syncthreads();                             // the ONLY block barrier

        // epilogue: reduce 16 partials, tanh, dual store
        float v = xp + bsum;
#pragma unroll
        for (int k = 0; k < NWARP; k++)
            v += sb[k * (RSZ * SST) + er * SST + ec];
        v = wmma::__float_to_tf32(tanhf(v));
        __stcg(outs + ooff, v);
        __stcg(&g_hswz[t & 1][swz_off], v);
        if (carry != nullptr && t == T_STEPS - 1)
            __stcg(carry + (size_t)(r0 + er) * H_SZ + j0 + ec, v);

        __syncwarp();                                // warp's stores all issued
        if (lane == 0) strel(myflag, base + (unsigned)(t + 1));
    }
}

// ---------------------------------------------------------------------------
extern "C" void kernel_launch(void* const* d_in, const int* in_sizes, int n_in,
                              void* d_out, int out_size) {
    const float* init = (const float*)d_in[0];
    const float* xs   = (const float*)d_in[1];
    const float* Wih  = (const float*)d_in[2];
    const float* bih  = (const float*)d_in[3];
    const float* Whh  = (const float*)d_in[4];
    const float* bhh  = (const float*)d_in[5];

    float* out   = (float*)d_out;
    float* carry = nullptr;
    float* outs;
    if (out_size == BH + TBH) { carry = out; outs = out + BH; }
    else                      { outs = out; }

    swizzle_init<<<BH / 256, 256>>>(init);

    int xsmem = (2 * 128 * 36 + 2 * 32 * 136) * (int)sizeof(float);   // 71680B
    cudaFuncSetAttribute(xproj_gemm, cudaFuncAttributeMaxDynamicSharedMemorySize, xsmem);
    xproj_gemm<<<dim3(H_SZ / 128, (T_STEPS * B_SZ) / 128), 256, xsmem>>>(xs, Wih, outs);

    int ssmem = 2 * NWARP * RSZ * SST * (int)sizeof(float);           // 73728B
    cudaFuncSetAttribute(rnn_scan, cudaFuncAttributeMaxDynamicSharedMemorySize, ssmem);
    rnn_scan<<<NBLK, 512, ssmem>>>(Whh, bih, bhh, outs, carry);
}